// round 1
// baseline (speedup 1.0000x reference)
#include <cuda_runtime.h>

#define DIM 4096
#define NTHREADS 256

// FWHT over rows of 4096 fp32, scaled by 1/64.
// One CTA per row. Thread t owns elements i = t*16 + k (k=0..15).
//  - stages 0-3  (bits 0-3 of i): in-register FWHT16
//  - stages 4-8  (bits 4-8 = lane bits 0-4): shfl_xor butterflies
//  - stages 9-11 (bits 9-11 = warp bits): one swizzled smem exchange,
//    then local FWHT8 over the m dimension, scale, coalesced store.
__global__ void __launch_bounds__(NTHREADS)
fwht4096_kernel(const float* __restrict__ x, float* __restrict__ out)
{
    __shared__ float sm[DIM];

    const int t = threadIdx.x;
    const long long row = blockIdx.x;
    const float* __restrict__ px = x + row * (long long)DIM + t * 16;

    float v[16];
    {
        const float4* p4 = reinterpret_cast<const float4*>(px);
        float4 a0 = p4[0], a1 = p4[1], a2 = p4[2], a3 = p4[3];
        v[0]  = a0.x; v[1]  = a0.y; v[2]  = a0.z; v[3]  = a0.w;
        v[4]  = a1.x; v[5]  = a1.y; v[6]  = a1.z; v[7]  = a1.w;
        v[8]  = a2.x; v[9]  = a2.y; v[10] = a2.z; v[11] = a2.w;
        v[12] = a3.x; v[13] = a3.y; v[14] = a3.z; v[15] = a3.w;
    }

    // ---- stages 0-3: local FWHT16 ----
    #pragma unroll
    for (int s = 0; s < 4; ++s) {
        const int h = 1 << s;
        #pragma unroll
        for (int j = 0; j < 16; ++j) {
            if ((j & h) == 0) {
                float a = v[j], b = v[j + h];
                v[j]     = a + b;
                v[j + h] = a - b;
            }
        }
    }

    // ---- stages 4-8: cross-lane butterflies via shfl_xor ----
    #pragma unroll
    for (int s = 0; s < 5; ++s) {
        const int mask = 1 << s;
        const float sgn = ((t >> s) & 1) ? -1.0f : 1.0f;
        #pragma unroll
        for (int j = 0; j < 16; ++j) {
            float other = __shfl_xor_sync(0xffffffffu, v[j], mask);
            // bit==0 lane: v+other ; bit==1 lane: other-v
            v[j] = fmaf(sgn, v[j], other);
        }
    }

    // ---- smem exchange for stages 9-11 ----
    // swizzle: word index i stored at i ^ (((i>>5)&3)<<2)  (XOR chunk bits 2-3
    // with bits 5-6) -> conflict-free STS.128 writes AND conflict-free strided
    // float2 reads.
    {
        const int base = t * 16;
        const int cx = (t >> 1) & 3;
        #pragma unroll
        for (int c = 0; c < 4; ++c) {
            float4 w = make_float4(v[4*c + 0], v[4*c + 1], v[4*c + 2], v[4*c + 3]);
            *reinterpret_cast<float4*>(&sm[base + 4 * (c ^ cx)]) = w;
        }
    }
    __syncthreads();

    // thread t now owns L = 2t and 2t+1 (bits 0-8), gathers all 8 values of
    // bits 9-11 (m) for each.
    float g0[8], g1[8];
    #pragma unroll
    for (int m = 0; m < 8; ++m) {
        int idx  = m * 512 + 2 * t;
        int sidx = idx ^ ((((unsigned)idx >> 5) & 3) << 2);
        float2 val = *reinterpret_cast<const float2*>(&sm[sidx]);
        g0[m] = val.x;
        g1[m] = val.y;
    }

    // ---- stages 9-11: local FWHT8 over m ----
    #pragma unroll
    for (int s = 0; s < 3; ++s) {
        const int h = 1 << s;
        #pragma unroll
        for (int m = 0; m < 8; ++m) {
            if ((m & h) == 0) {
                float a = g0[m], b = g0[m + h];
                g0[m] = a + b;  g0[m + h] = a - b;
                float c = g1[m], d = g1[m + h];
                g1[m] = c + d;  g1[m + h] = c - d;
            }
        }
    }

    // ---- scale (exactly 1/64) and coalesced store ----
    const float SCALE = 0.015625f;  // (1/sqrt(4096)) / 1.0
    float* __restrict__ po = out + row * (long long)DIM;
    #pragma unroll
    for (int m = 0; m < 8; ++m) {
        float2 w = make_float2(g0[m] * SCALE, g1[m] * SCALE);
        *reinterpret_cast<float2*>(&po[m * 512 + 2 * t]) = w;
    }
}

extern "C" void kernel_launch(void* const* d_in, const int* in_sizes, int n_in,
                              void* d_out, int out_size)
{
    const float* x = (const float*)d_in[0];
    float* out = (float*)d_out;
    const int rows = in_sizes[0] / DIM;   // 4*2048 = 8192
    fwht4096_kernel<<<rows, NTHREADS>>>(x, out);
}

// round 2
// speedup vs baseline: 1.2429x; 1.2429x over previous
#include <cuda_runtime.h>

#define DIM 4096
#define NTHREADS 256

// FWHT-4096 over fp32 rows, scaled by 1/64. One CTA per row.
//
// Bit plan (element index i, bits e0..e11):
//   load: lane l loads float4 at 512w + 128c + 4l  (coalesced LDG.128)
//         -> thread locally owns e0,e1 (float-in-chunk) and e7,e8 (chunk c)
//   pass1: in-register FWHT16 over v-index bits = dims {e0,e1,e7,e8}
//   pass2: 5 half-exchange shuffle stages over lane bits (dims e2..e6),
//          each stage: 8 shfl + local add/sub, swapping lane-bit s with
//          register bit 3. Final physical map:
//            v0->e0 v1->e1 v2->e7 v3->e6 ; l0->e8 l1->e2 l2->e3 l3->e4 l4->e5
//          => smem index in NATURAL element order for bits 0..8.
//   pass3: one swizzled smem exchange, local FWHT8 over warp dims e9..e11,
//          scale, coalesced float2 stores.
__global__ void __launch_bounds__(NTHREADS)
fwht4096_kernel(const float* __restrict__ x, float* __restrict__ out)
{
    __shared__ float sm[DIM];

    const int t = threadIdx.x;
    const int l = t & 31;
    const int w = t >> 5;
    const long long row = blockIdx.x;

    const float* __restrict__ px = x + row * (long long)DIM + 512 * w + 4 * l;

    float v[16];
    #pragma unroll
    for (int c = 0; c < 4; ++c) {
        float4 a = *reinterpret_cast<const float4*>(px + 128 * c);
        v[4*c + 0] = a.x; v[4*c + 1] = a.y;
        v[4*c + 2] = a.z; v[4*c + 3] = a.w;
    }

    // ---- pass1: local FWHT16 over v-index bits (dims e0,e1,e7,e8) ----
    #pragma unroll
    for (int s = 0; s < 4; ++s) {
        const int h = 1 << s;
        #pragma unroll
        for (int j = 0; j < 16; ++j) {
            if ((j & h) == 0) {
                float a = v[j], b = v[j + h];
                v[j]     = a + b;
                v[j + h] = a - b;
            }
        }
    }

    // ---- pass2: 5 half-exchange shuffle stages (dims e2..e6) ----
    // Stage s: butterfly across lane bit s; exchange only 8 regs; the
    // transformed dim lands in register bit 3, old reg-bit-3 dim moves to
    // the lane bit. "+" result goes to the bit=0 position (Sylvester order).
    #pragma unroll
    for (int s = 0; s < 5; ++s) {
        const unsigned m = 1u << s;
        const int p = (l >> s) & 1;                  // this thread's lane bit
        const unsigned nm = (unsigned)p << 31;       // sign-flip mask for diff
        #pragma unroll
        for (int j = 0; j < 8; ++j) {
            float send = p ? v[j]     : v[j + 8];
            float keep = p ? v[j + 8] : v[j];
            float r = __shfl_xor_sync(0xffffffffu, send, m);
            float sum  = keep + r;                   // a+b on both sides
            float diff = keep - r;                   // +-(a-b); fix sign below
            v[j]     = sum;
            v[j + 8] = __uint_as_float(__float_as_uint(diff) ^ nm);
        }
    }

    // ---- smem write (natural element order, bank swizzle) ----
    // value v[j] (j = j0+2j1+4j2+8j3) is element
    //   i = j0 + 2*j1 + 4*l1 + 8*l2 + 16*l3 + 32*l4 + 64*j3 + 128*j2
    //       + 256*l0 + 512*w
    // Four float4 runs per thread at offsets {0,128,64,192} for k=j3*2+j2.
    {
        const int hb = (l >> 1) & 15;
        const int p0 = l & 1;
        const int wbase = 512 * w + 4 * hb + 256 * p0;
        const int offs[4] = {0, 128, 64, 192};
        #pragma unroll
        for (int k = 0; k < 4; ++k) {
            int a = wbase + offs[k];
            a ^= ((a >> 8) & 1) << 4;   // bank swizzle
            *reinterpret_cast<float4*>(&sm[a]) =
                make_float4(v[4*k + 0], v[4*k + 1], v[4*k + 2], v[4*k + 3]);
        }
    }
    __syncthreads();

    // ---- pass3: gather two lanes of the e9..e11 dimension ----
    float g0[8], g1[8];
    #pragma unroll
    for (int m = 0; m < 8; ++m) {
        int a = 2 * t + 512 * m;
        a ^= ((a >> 8) & 1) << 4;       // same swizzle
        float2 q = *reinterpret_cast<const float2*>(&sm[a]);
        g0[m] = q.x;
        g1[m] = q.y;
    }

    #pragma unroll
    for (int s = 0; s < 3; ++s) {
        const int h = 1 << s;
        #pragma unroll
        for (int m = 0; m < 8; ++m) {
            if ((m & h) == 0) {
                float a = g0[m], b = g0[m + h];
                g0[m] = a + b;  g0[m + h] = a - b;
                float c = g1[m], d = g1[m + h];
                g1[m] = c + d;  g1[m + h] = c - d;
            }
        }
    }

    // ---- scale (exact 1/64) + coalesced store ----
    const float SCALE = 0.015625f;
    float* __restrict__ po = out + row * (long long)DIM + 2 * t;
    #pragma unroll
    for (int m = 0; m < 8; ++m) {
        float2 q = make_float2(g0[m] * SCALE, g1[m] * SCALE);
        *reinterpret_cast<float2*>(&po[512 * m]) = q;
    }
}

extern "C" void kernel_launch(void* const* d_in, const int* in_sizes, int n_in,
                              void* d_out, int out_size)
{
    const float* x = (const float*)d_in[0];
    float* out = (float*)d_out;
    const int rows = in_sizes[0] / DIM;   // 8192
    fwht4096_kernel<<<rows, NTHREADS>>>(x, out);
}

// round 3
// speedup vs baseline: 1.2755x; 1.0262x over previous
#include <cuda_runtime.h>

#define DIM 4096
#define NTHREADS 256

// FWHT-4096, one CTA per row, zero shuffles.
//   pass1: local FWHT16 over {e0,e1,e10,e11}  (float4 loads at i=4t+1024c)
//   ex1:   smem gather of {e2..e5} (stride-4), local FWHT16, in-place writeback
//   ex2:   smem gather of {e6..e9} (stride-64), local FWHT16, scale, store
// Swizzle phys = L ^ (((L>>6)&7)<<2) makes every access conflict-free.
__global__ void __launch_bounds__(NTHREADS)
fwht4096_kernel(const float* __restrict__ x, float* __restrict__ out)
{
    __shared__ float sm[DIM];

    const int t = threadIdx.x;
    const long long row = blockIdx.x;
    const float* __restrict__ px = x + row * (long long)DIM + 4 * t;

    float v[16];
    #pragma unroll
    for (int c = 0; c < 4; ++c) {
        float4 a = *reinterpret_cast<const float4*>(px + 1024 * c);
        v[4*c+0] = a.x; v[4*c+1] = a.y; v[4*c+2] = a.z; v[4*c+3] = a.w;
    }

    // ---- pass1: FWHT16 over v-index bits (dims e0,e1,e10,e11) ----
    #pragma unroll
    for (int s = 0; s < 4; ++s) {
        const int h = 1 << s;
        #pragma unroll
        for (int j = 0; j < 16; ++j) {
            if ((j & h) == 0) {
                float a = v[j], b = v[j + h];
                v[j]     = a + b;
                v[j + h] = a - b;
            }
        }
    }

    // ---- exchange 1 write: float4 at logical 4t+1024c, swizzled ----
    {
        const int wb = (4 * t) ^ ((((4 * t) >> 6) & 7) << 2);  // flips const bits
        #pragma unroll
        for (int c = 0; c < 4; ++c) {
            *reinterpret_cast<float4*>(&sm[wb + 1024 * c]) =
                make_float4(v[4*c+0], v[4*c+1], v[4*c+2], v[4*c+3]);
        }
    }
    __syncthreads();

    // ---- exchange 1 read: gather dims e2..e5 (stride 4 words) ----
    // logical L = (t&3) + 4n + 64*((t>>2)&15) + 1024*(t>>6)
    // phys = base + (4n ^ X),  X = ((t>>2)&7)<<2  (runtime-constant XOR)
    const int base1 = (t & 3) + 64 * ((t >> 2) & 15) + 1024 * (t >> 6);
    const int X = ((t >> 2) & 7) << 2;
    float g[16];
    int adr[16];
    #pragma unroll
    for (int n = 0; n < 16; ++n) {
        adr[n] = base1 + ((4 * n) ^ X);
        g[n] = sm[adr[n]];
    }

    // FWHT16 over n (dims e2..e5)
    #pragma unroll
    for (int s = 0; s < 4; ++s) {
        const int h = 1 << s;
        #pragma unroll
        for (int j = 0; j < 16; ++j) {
            if ((j & h) == 0) {
                float a = g[j], b = g[j + h];
                g[j]     = a + b;
                g[j + h] = a - b;
            }
        }
    }

    // in-place writeback (per-thread-disjoint slots: no barrier needed before)
    #pragma unroll
    for (int n = 0; n < 16; ++n) sm[adr[n]] = g[n];
    __syncthreads();

    // ---- exchange 2 read: gather dims e6..e9 (stride 64 words) ----
    // logical L = (t&63) + 64m + 1024*(t>>6); phys = (base2 ^ 4*(m&7)) + 64m
    const int base2 = (t & 63) + 1024 * (t >> 6);
    float hv[16];
    #pragma unroll
    for (int m = 0; m < 16; ++m) {
        hv[m] = sm[(base2 ^ (4 * (m & 7))) + 64 * m];
    }

    // FWHT16 over m (dims e6..e9)
    #pragma unroll
    for (int s = 0; s < 4; ++s) {
        const int h = 1 << s;
        #pragma unroll
        for (int j = 0; j < 16; ++j) {
            if ((j & h) == 0) {
                float a = hv[j], b = hv[j + h];
                hv[j]     = a + b;
                hv[j + h] = a - b;
            }
        }
    }

    // ---- scale (exact 1/64) + perfectly coalesced stores (128B/instr) ----
    const float SCALE = 0.015625f;
    float* __restrict__ po = out + row * (long long)DIM + base2;
    #pragma unroll
    for (int m = 0; m < 16; ++m) {
        po[64 * m] = hv[m] * SCALE;
    }
}

extern "C" void kernel_launch(void* const* d_in, const int* in_sizes, int n_in,
                              void* d_out, int out_size)
{
    const float* x = (const float*)d_in[0];
    float* out = (float*)d_out;
    const int rows = in_sizes[0] / DIM;   // 8192
    fwht4096_kernel<<<rows, NTHREADS>>>(x, out);
}

// round 4
// speedup vs baseline: 1.2792x; 1.0029x over previous
#include <cuda_runtime.h>

#define DIM 4096
#define NTHREADS 256

// FWHT-4096, one CTA per row, zero shuffles, <=32 regs (8 CTAs/SM).
//   pass1: local FWHT16 over {e0,e1,e10,e11}  (float4 loads at i=4t+1024c)
//   ex1:   smem gather of {e2..e5} (stride-4), local FWHT16, in-place writeback
//          addresses: P ^ 4n with P = base1 ^ X  (base1 bits2-5 == 0)
//   ex2:   smem gather of {e6..e9} (stride-64), local FWHT16, scale, store
// Global swizzle phys = L ^ (((L>>6)&7)<<2): conflict-free everywhere.
__global__ void __launch_bounds__(NTHREADS, 8)
fwht4096_kernel(const float* __restrict__ x, float* __restrict__ out)
{
    __shared__ float sm[DIM];

    const int t = threadIdx.x;
    const long long row = blockIdx.x;
    const float* __restrict__ px = x + row * (long long)DIM + 4 * t;

    float v[16];
    #pragma unroll
    for (int c = 0; c < 4; ++c) {
        float4 a = *reinterpret_cast<const float4*>(px + 1024 * c);
        v[4*c+0] = a.x; v[4*c+1] = a.y; v[4*c+2] = a.z; v[4*c+3] = a.w;
    }

    // ---- pass1: FWHT16 over v-index bits (dims e0,e1,e10,e11) ----
    #pragma unroll
    for (int s = 0; s < 4; ++s) {
        const int h = 1 << s;
        #pragma unroll
        for (int j = 0; j < 16; ++j) {
            if ((j & h) == 0) {
                float a = v[j], b = v[j + h];
                v[j]     = a + b;
                v[j + h] = a - b;
            }
        }
    }

    // ---- exchange 1 write: float4 at logical 4t+1024c, swizzled ----
    {
        const int wb = (4 * t) ^ (((t >> 4) & 7) << 2);
        #pragma unroll
        for (int c = 0; c < 4; ++c) {
            *reinterpret_cast<float4*>(&sm[wb + 1024 * c]) =
                make_float4(v[4*c+0], v[4*c+1], v[4*c+2], v[4*c+3]);
        }
    }
    __syncthreads();

    // ---- exchange 1: gather dims e2..e5 (stride-4 words), swizzled ----
    // logical L = (t&3) + 4n + 64*((t>>2)&15) + 1024*(t>>6)
    // phys     = P ^ 4n,  P = base1 ^ X  (base1 bits 2-5 are zero)
    const int base1 = (t & 3) + 64 * ((t >> 2) & 15) + 1024 * (t >> 6);
    const int P = base1 ^ (((t >> 2) & 7) << 2);
    #pragma unroll
    for (int n = 0; n < 16; ++n) v[n] = sm[P ^ (4 * n)];

    // FWHT16 over n (dims e2..e5)
    #pragma unroll
    for (int s = 0; s < 4; ++s) {
        const int h = 1 << s;
        #pragma unroll
        for (int j = 0; j < 16; ++j) {
            if ((j & h) == 0) {
                float a = v[j], b = v[j + h];
                v[j]     = a + b;
                v[j + h] = a - b;
            }
        }
    }

    // in-place writeback (per-thread-disjoint slots)
    #pragma unroll
    for (int n = 0; n < 16; ++n) sm[P ^ (4 * n)] = v[n];
    __syncthreads();

    // ---- exchange 2: gather dims e6..e9 (stride-64 words), swizzled ----
    // logical L = (t&63) + 64m + 1024*(t>>6); phys = (base2 ^ 4*(m&7)) + 64m
    const int base2 = (t & 63) + 1024 * (t >> 6);
    #pragma unroll
    for (int m = 0; m < 16; ++m) {
        v[m] = sm[(base2 ^ (4 * (m & 7))) + 64 * m];
    }

    // FWHT16 over m (dims e6..e9)
    #pragma unroll
    for (int s = 0; s < 4; ++s) {
        const int h = 1 << s;
        #pragma unroll
        for (int j = 0; j < 16; ++j) {
            if ((j & h) == 0) {
                float a = v[j], b = v[j + h];
                v[j]     = a + b;
                v[j + h] = a - b;
            }
        }
    }

    // ---- scale (exact 1/64) + perfectly coalesced stores ----
    const float SCALE = 0.015625f;
    float* __restrict__ po = out + row * (long long)DIM + base2;
    #pragma unroll
    for (int m = 0; m < 16; ++m) {
        po[64 * m] = v[m] * SCALE;
    }
}

extern "C" void kernel_launch(void* const* d_in, const int* in_sizes, int n_in,
                              void* d_out, int out_size)
{
    const float* x = (const float*)d_in[0];
    float* out = (float*)d_out;
    const int rows = in_sizes[0] / DIM;   // 8192
    fwht4096_kernel<<<rows, NTHREADS>>>(x, out);
}